// round 5
// baseline (speedup 1.0000x reference)
#include <cuda_runtime.h>
#include <cuda_fp16.h>

#define BATCH   32768
#define PIECES  32
#define NNZ     (BATCH * PIECES)
#define FT      512
#define NF      768
#define CHUNK   128              // output channels per chunk
#define NCHUNK  (FT / CHUNK)     // 4
#define ROWB    (CHUNK * 2)      // bytes per feature row in smem (fp16) = 256
#define NBLK    37               // blocks per chunk: 4*37 = 148 = #SMs

// ---------------- device scratch (no allocations allowed) ----------------
__device__ __half g_Wt[NF * FT];          // transposed fp16 weights [feat][out]
__device__ int    g_pack[NNZ];            // stm col | nstm col << 10
__device__ __half g_valh[NNZ];            // values in fp16 (general path)
__device__ int    g_allones;              // 1 if all values == 1.0f
__device__ float  g_partial[NCHUNK * BATCH];

// ---------------- prep: tiled transpose ft_w [512,768] -> [768,512] fp16 --
__global__ void prep_w(const float* __restrict__ ft_w) {
    __shared__ float tile[32][33];
    const int tx = threadIdx.x, ty = threadIdx.y;       // 32 x 8
    const int fb = blockIdx.x * 32;                     // feature tile base
    const int kb = blockIdx.y * 32;                     // channel tile base
    if (blockIdx.x == 0 && blockIdx.y == 0 && tx == 0 && ty == 0)
        g_allones = 1;                                  // reset before prep_idx
    #pragma unroll
    for (int i = 0; i < 32; i += 8)
        tile[ty + i][tx] = ft_w[(kb + ty + i) * NF + fb + tx];   // coalesced in f
    __syncthreads();
    #pragma unroll
    for (int i = 0; i < 32; i += 8)
        g_Wt[(fb + ty + i) * FT + kb + tx] = __float2half(tile[tx][ty + i]);
}

// ---------------- prep: pack columns, convert values ---------------------
// Index dtype sniffed at runtime: row 0 is repeat(arange(B), 32), so an int32
// view has [64]=1,[65]=0 iff little-endian int64, [64]=2,[65]=2 iff int32.
__global__ void prep_idx(const int* __restrict__ stm32,
                         const int* __restrict__ nstm32,
                         const float* __restrict__ vals) {
    const bool is64 = (stm32[64] == 1 && stm32[65] == 0);
    int i = blockIdx.x * blockDim.x + threadIdx.x;
    if (i < NNZ) {
        int cs, cn;
        if (is64) {
            cs = stm32[2 * (NNZ + i)];      // low word of int64 col
            cn = nstm32[2 * (NNZ + i)];
        } else {
            cs = stm32[NNZ + i];
            cn = nstm32[NNZ + i];
        }
        g_pack[i] = cs | (cn << 10);
        float v = vals[i];
        g_valh[i] = __float2half(v);
        if (v != 1.0f) g_allones = 0;       // benign race: only writes 0
    }
}

// ---------------- main: gather-accumulate from smem-resident W chunk -----
// Two positions per loop iteration: identical crossbar bytes, but the two
// 5-level shfl-reduce chains interleave -> serial tail per position halved.
__global__ void __launch_bounds__(512, 1)
main_k(const float* __restrict__ ft_b, const float* __restrict__ out_w) {
    extern __shared__ __half sW[];   // [NF][CHUNK] fp16 = 192 KB
    const int chunk = blockIdx.y;
    const int tid = threadIdx.x;

    // stage W chunk: 12288 uint4 copies
    {
        uint4* dst = (uint4*)sW;
        for (int i = tid; i < NF * (CHUNK / 8); i += blockDim.x) {
            int f = i >> 4;          // feature
            int q = i & 15;          // 16B quad within row
            dst[i] = ((const uint4*)(g_Wt + f * FT + chunk * CHUNK))[q];
        }
    }
    __syncthreads();

    const int warp = tid >> 5, lane = tid & 31;
    const int gw = blockIdx.x * (blockDim.x >> 5) + warp;
    const int stride = gridDim.x * (blockDim.x >> 5);

    const char* sbase = (const char*)sW + lane * 8;   // lane's 8B within a row

    // loop-invariant epilogue coefficients for this lane's 4 channels
    const int ch = chunk * CHUNK + lane * 4;
    const float4 bb = *(const float4*)(ft_b + ch);
    const float4 ws = *(const float4*)(out_w + ch);
    const float4 wn = *(const float4*)(out_w + FT + ch);

    const __half2 hz = __float2half2_rn(0.f);
    const int ones = g_allones;          // uniform branch

    for (int b = gw * 2; b < BATCH; b += stride * 2) {
        const int pk1 = g_pack[b * PIECES + lane];
        const int pk2 = g_pack[(b + 1) * PIECES + lane];

        // position 1 accumulators (even/odd piece banks)
        __half2 xS0a = hz, xS1a = hz, xS0b = hz, xS1b = hz;
        __half2 xN0a = hz, xN1a = hz, xN0b = hz, xN1b = hz;
        // position 2 accumulators
        __half2 yS0a = hz, yS1a = hz, yS0b = hz, yS1b = hz;
        __half2 yN0a = hz, yN1a = hz, yN0b = hz, yN1b = hz;

        if (ones) {
            #pragma unroll
            for (int j = 0; j < PIECES; j++) {
                int p1 = __shfl_sync(0xffffffffu, pk1, j);
                int p2 = __shfl_sync(0xffffffffu, pk2, j);
                uint2 dS1 = *(const uint2*)(sbase + ((p1 & 1023) << 8));
                uint2 dN1 = *(const uint2*)(sbase + (((p1 >> 10) & 1023) << 8));
                uint2 dS2 = *(const uint2*)(sbase + ((p2 & 1023) << 8));
                uint2 dN2 = *(const uint2*)(sbase + (((p2 >> 10) & 1023) << 8));
                if (j & 1) {
                    xS0b = __hadd2(xS0b, *(__half2*)&dS1.x); xS1b = __hadd2(xS1b, *(__half2*)&dS1.y);
                    xN0b = __hadd2(xN0b, *(__half2*)&dN1.x); xN1b = __hadd2(xN1b, *(__half2*)&dN1.y);
                    yS0b = __hadd2(yS0b, *(__half2*)&dS2.x); yS1b = __hadd2(yS1b, *(__half2*)&dS2.y);
                    yN0b = __hadd2(yN0b, *(__half2*)&dN2.x); yN1b = __hadd2(yN1b, *(__half2*)&dN2.y);
                } else {
                    xS0a = __hadd2(xS0a, *(__half2*)&dS1.x); xS1a = __hadd2(xS1a, *(__half2*)&dS1.y);
                    xN0a = __hadd2(xN0a, *(__half2*)&dN1.x); xN1a = __hadd2(xN1a, *(__half2*)&dN1.y);
                    yS0a = __hadd2(yS0a, *(__half2*)&dS2.x); yS1a = __hadd2(yS1a, *(__half2*)&dS2.y);
                    yN0a = __hadd2(yN0a, *(__half2*)&dN2.x); yN1a = __hadd2(yN1a, *(__half2*)&dN2.y);
                }
            }
        } else {
            const unsigned v1 = (unsigned)__half_as_ushort(g_valh[b * PIECES + lane]);
            const unsigned v2 = (unsigned)__half_as_ushort(g_valh[(b + 1) * PIECES + lane]);
            #pragma unroll
            for (int j = 0; j < PIECES; j++) {
                int p1 = __shfl_sync(0xffffffffu, pk1, j);
                int p2 = __shfl_sync(0xffffffffu, pk2, j);
                unsigned w1 = __shfl_sync(0xffffffffu, v1, j);
                unsigned w2 = __shfl_sync(0xffffffffu, v2, j);
                __half2 q1 = __half2half2(__ushort_as_half((unsigned short)w1));
                __half2 q2 = __half2half2(__ushort_as_half((unsigned short)w2));
                uint2 dS1 = *(const uint2*)(sbase + ((p1 & 1023) << 8));
                uint2 dN1 = *(const uint2*)(sbase + (((p1 >> 10) & 1023) << 8));
                uint2 dS2 = *(const uint2*)(sbase + ((p2 & 1023) << 8));
                uint2 dN2 = *(const uint2*)(sbase + (((p2 >> 10) & 1023) << 8));
                if (j & 1) {
                    xS0b = __hfma2(*(__half2*)&dS1.x, q1, xS0b); xS1b = __hfma2(*(__half2*)&dS1.y, q1, xS1b);
                    xN0b = __hfma2(*(__half2*)&dN1.x, q1, xN0b); xN1b = __hfma2(*(__half2*)&dN1.y, q1, xN1b);
                    yS0b = __hfma2(*(__half2*)&dS2.x, q2, yS0b); yS1b = __hfma2(*(__half2*)&dS2.y, q2, yS1b);
                    yN0b = __hfma2(*(__half2*)&dN2.x, q2, yN0b); yN1b = __hfma2(*(__half2*)&dN2.y, q2, yN1b);
                } else {
                    xS0a = __hfma2(*(__half2*)&dS1.x, q1, xS0a); xS1a = __hfma2(*(__half2*)&dS1.y, q1, xS1a);
                    xN0a = __hfma2(*(__half2*)&dN1.x, q1, xN0a); xN1a = __hfma2(*(__half2*)&dN1.y, q1, xN1a);
                    yS0a = __hfma2(*(__half2*)&dS2.x, q2, yS0a); yS1a = __hfma2(*(__half2*)&dS2.y, q2, yS1a);
                    yN0a = __hfma2(*(__half2*)&dN2.x, q2, yN0a); yN1a = __hfma2(*(__half2*)&dN2.y, q2, yN1a);
                }
            }
        }

        // combine banks in fp32 and form per-lane partial logits
        float r1, r2;
        {
            float2 fS0a = __half22float2(xS0a), fS0b = __half22float2(xS0b);
            float2 fS1a = __half22float2(xS1a), fS1b = __half22float2(xS1b);
            float2 fN0a = __half22float2(xN0a), fN0b = __half22float2(xN0b);
            float2 fN1a = __half22float2(xN1a), fN1b = __half22float2(xN1b);
            float r = 0.f;
            r += __saturatef(fS0a.x + fS0b.x + bb.x) * ws.x;
            r += __saturatef(fS0a.y + fS0b.y + bb.y) * ws.y;
            r += __saturatef(fS1a.x + fS1b.x + bb.z) * ws.z;
            r += __saturatef(fS1a.y + fS1b.y + bb.w) * ws.w;
            r += __saturatef(fN0a.x + fN0b.x + bb.x) * wn.x;
            r += __saturatef(fN0a.y + fN0b.y + bb.y) * wn.y;
            r += __saturatef(fN1a.x + fN1b.x + bb.z) * wn.z;
            r += __saturatef(fN1a.y + fN1b.y + bb.w) * wn.w;
            r1 = r;
        }
        {
            float2 fS0a = __half22float2(yS0a), fS0b = __half22float2(yS0b);
            float2 fS1a = __half22float2(yS1a), fS1b = __half22float2(yS1b);
            float2 fN0a = __half22float2(yN0a), fN0b = __half22float2(yN0b);
            float2 fN1a = __half22float2(yN1a), fN1b = __half22float2(yN1b);
            float r = 0.f;
            r += __saturatef(fS0a.x + fS0b.x + bb.x) * ws.x;
            r += __saturatef(fS0a.y + fS0b.y + bb.y) * ws.y;
            r += __saturatef(fS1a.x + fS1b.x + bb.z) * ws.z;
            r += __saturatef(fS1a.y + fS1b.y + bb.w) * ws.w;
            r += __saturatef(fN0a.x + fN0b.x + bb.x) * wn.x;
            r += __saturatef(fN0a.y + fN0b.y + bb.y) * wn.y;
            r += __saturatef(fN1a.x + fN1b.x + bb.z) * wn.z;
            r += __saturatef(fN1a.y + fN1b.y + bb.w) * wn.w;
            r2 = r;
        }

        // two independent butterflies, interleaved -> latency overlapped
        #pragma unroll
        for (int d = 16; d > 0; d >>= 1) {
            r1 += __shfl_xor_sync(0xffffffffu, r1, d);
            r2 += __shfl_xor_sync(0xffffffffu, r2, d);
        }

        if (lane == 0) {
            g_partial[chunk * BATCH + b]     = r1;
            g_partial[chunk * BATCH + b + 1] = r2;
        }
    }
}

// ---------------- epilogue: sum partials + sigmoid (float4) --------------
__global__ void epi_k(const float* __restrict__ out_b, float* __restrict__ out) {
    int t = blockIdx.x * blockDim.x + threadIdx.x;    // 8192 threads, 4 b each
    if (t < BATCH / 4) {
        const float bias = out_b[0];
        float4 s = ((const float4*)g_partial)[t];
        #pragma unroll
        for (int c = 1; c < NCHUNK; c++) {
            float4 p = ((const float4*)(g_partial + c * BATCH))[t];
            s.x += p.x; s.y += p.y; s.z += p.z; s.w += p.w;
        }
        float4 o;
        o.x = 1.f / (1.f + __expf(-(s.x + bias)));
        o.y = 1.f / (1.f + __expf(-(s.y + bias)));
        o.z = 1.f / (1.f + __expf(-(s.z + bias)));
        o.w = 1.f / (1.f + __expf(-(s.w + bias)));
        ((float4*)out)[t] = o;
    }
}

// ---------------- launch --------------------------------------------------
extern "C" void kernel_launch(void* const* d_in, const int* in_sizes, int n_in,
                              void* d_out, int out_size) {
    // Fixed leading inputs (dict order): stm_indices, nstm_indices, values.
    const int*   stm  = (const int*)d_in[0];   // [2, NNZ] int32 or int64 (sniffed)
    const int*   nstm = (const int*)d_in[1];
    const float* vals = (const float*)d_in[2];

    // Trailing inputs mapped by element count ("size" may or may not be a
    // real buffer). out_b is the LAST size-1 entry (dict order: size < out_b).
    const float* ft_w  = 0;
    const float* ft_b  = 0;
    const float* out_w = 0;
    const float* out_b = 0;
    for (int i = 3; i < n_in; i++) {
        int s = in_sizes[i];
        if      (s == NF * FT) ft_w  = (const float*)d_in[i];
        else if (s == FT)      ft_b  = (const float*)d_in[i];
        else if (s == 2 * FT)  out_w = (const float*)d_in[i];
        else if (s == 1)       out_b = (const float*)d_in[i];  // last wins
    }
    float* out = (float*)d_out;                  // [B, 1] float32

    prep_w<<<dim3(NF / 32, FT / 32), dim3(32, 8)>>>(ft_w);
    prep_idx<<<(NNZ + 255) / 256, 256>>>(stm, nstm, vals);

    const int SMEM = NF * CHUNK * 2;   // 192 KB
    cudaFuncSetAttribute(main_k, cudaFuncAttributeMaxDynamicSharedMemorySize, SMEM);
    main_k<<<dim3(NBLK, NCHUNK), 512, SMEM>>>(ft_b, out_w);

    epi_k<<<(BATCH / 4 + 127) / 128, 128>>>(out_b, out);
}

// round 6
// speedup vs baseline: 1.0556x; 1.0556x over previous
#include <cuda_runtime.h>
#include <cuda_fp16.h>

#define BATCH   32768
#define PIECES  32
#define NNZ     (BATCH * PIECES)
#define FT      512
#define NF      768
#define CHUNK   128              // output channels per chunk
#define NCHUNK  (FT / CHUNK)     // 4
#define NBLK    37               // blocks per chunk: 4*37 = 148 = #SMs

// ---------------- device scratch (no allocations allowed) ----------------
__device__ __half g_Wt[NF * FT];          // transposed fp16 weights [feat][out]
__device__ float  g_partial[NCHUNK * BATCH];

// ---------------- prep: tiled transpose ft_w [512,768] -> [768,512] fp16 --
__global__ void prep_w(const float* __restrict__ ft_w) {
    __shared__ float tile[32][33];
    const int tx = threadIdx.x, ty = threadIdx.y;       // 32 x 8
    const int fb = blockIdx.x * 32;                     // feature tile base
    const int kb = blockIdx.y * 32;                     // channel tile base
    #pragma unroll
    for (int i = 0; i < 32; i += 8)
        tile[ty + i][tx] = ft_w[(kb + ty + i) * NF + fb + tx];   // coalesced in f
    __syncthreads();
    #pragma unroll
    for (int i = 0; i < 32; i += 8)
        g_Wt[(fb + ty + i) * FT + kb + tx] = __float2half(tile[tx][ty + i]);
}

// ---------------- main: gather-accumulate from smem-resident W chunk -----
// R4 proven loop shape (warp-wide uint2 row reads, one packed SHFL/piece).
// Index prep folded in: raw int64/int32 columns read directly per position;
// per-warp vote selects the all-ones (HADD2) fast path.
__global__ void __launch_bounds__(512, 1)
main_k(const int* __restrict__ stm32, const int* __restrict__ nstm32,
       const float* __restrict__ vals,
       const float* __restrict__ ft_b, const float* __restrict__ out_w) {
    extern __shared__ __half sW[];   // [NF][CHUNK] fp16 = 192 KB
    const int chunk = blockIdx.y;
    const int tid = threadIdx.x;

    // stage W chunk: 12288 uint4 copies
    {
        uint4* dst = (uint4*)sW;
        for (int i = tid; i < NF * (CHUNK / 8); i += blockDim.x) {
            int f = i >> 4;          // feature
            int q = i & 15;          // 16B quad within row
            dst[i] = ((const uint4*)(g_Wt + f * FT + chunk * CHUNK))[q];
        }
    }
    __syncthreads();

    const int warp = tid >> 5, lane = tid & 31;
    const int gw = blockIdx.x * (blockDim.x >> 5) + warp;
    const int stride = gridDim.x * (blockDim.x >> 5);

    // dtype sniff: row 0 of indices is repeat(arange(B),32); an int32 view has
    // [64]=1,[65]=0 iff little-endian int64, [64]=2,[65]=2 iff int32.
    const bool is64 = (stm32[64] == 1 && stm32[65] == 0);

    const char* sbase = (const char*)sW + lane * 8;   // lane's 8B within a row

    // loop-invariant epilogue coefficients for this lane's 4 channels
    const int ch = chunk * CHUNK + lane * 4;
    const float4 bb = *(const float4*)(ft_b + ch);
    const float4 ws = *(const float4*)(out_w + ch);
    const float4 wn = *(const float4*)(out_w + FT + ch);

    const __half2 hz = __float2half2_rn(0.f);

    for (int b = gw; b < BATCH; b += stride) {
        const int base = b * PIECES + lane;

        // direct index/value loads (prep_idx folded in)
        int cs, cn;
        if (is64) {
            cs = stm32[2 * (NNZ + base)];      // low word of int64 col
            cn = nstm32[2 * (NNZ + base)];
        } else {
            cs = stm32[NNZ + base];
            cn = nstm32[NNZ + base];
        }
        const float v = vals[base];
        const int pk = (cs << 8) | (cn << 18);   // pre-shifted pack
        const bool ones = __all_sync(0xffffffffu, v == 1.0f);

        // split accumulator banks (even/odd pieces) to reduce fp16 walk
        __half2 aS0a = hz, aS1a = hz, aS0b = hz, aS1b = hz;
        __half2 aN0a = hz, aN1a = hz, aN0b = hz, aN1b = hz;

        if (ones) {
            #pragma unroll
            for (int j = 0; j < PIECES; j++) {
                int p = __shfl_sync(0xffffffffu, pk, j);
                uint2 dS = *(const uint2*)(sbase + (p & 0x3FF00));
                uint2 dN = *(const uint2*)(sbase + ((p >> 10) & 0x3FF00));
                __half2 s0 = *(__half2*)&dS.x;
                __half2 s1 = *(__half2*)&dS.y;
                __half2 n0 = *(__half2*)&dN.x;
                __half2 n1 = *(__half2*)&dN.y;
                if (j & 1) {
                    aS0b = __hadd2(aS0b, s0); aS1b = __hadd2(aS1b, s1);
                    aN0b = __hadd2(aN0b, n0); aN1b = __hadd2(aN1b, n1);
                } else {
                    aS0a = __hadd2(aS0a, s0); aS1a = __hadd2(aS1a, s1);
                    aN0a = __hadd2(aN0a, n0); aN1a = __hadd2(aN1a, n1);
                }
            }
        } else {
            const unsigned vv = (unsigned)__half_as_ushort(__float2half(v));
            #pragma unroll
            for (int j = 0; j < PIECES; j++) {
                int p = __shfl_sync(0xffffffffu, pk, j);
                unsigned vj = __shfl_sync(0xffffffffu, vv, j);
                __half2 v2 = __half2half2(__ushort_as_half((unsigned short)vj));
                uint2 dS = *(const uint2*)(sbase + (p & 0x3FF00));
                uint2 dN = *(const uint2*)(sbase + ((p >> 10) & 0x3FF00));
                __half2 s0 = *(__half2*)&dS.x;
                __half2 s1 = *(__half2*)&dS.y;
                __half2 n0 = *(__half2*)&dN.x;
                __half2 n1 = *(__half2*)&dN.y;
                if (j & 1) {
                    aS0b = __hfma2(s0, v2, aS0b); aS1b = __hfma2(s1, v2, aS1b);
                    aN0b = __hfma2(n0, v2, aN0b); aN1b = __hfma2(n1, v2, aN1b);
                } else {
                    aS0a = __hfma2(s0, v2, aS0a); aS1a = __hfma2(s1, v2, aS1a);
                    aN0a = __hfma2(n0, v2, aN0a); aN1a = __hfma2(n1, v2, aN1a);
                }
            }
        }

        // combine banks in fp32
        float2 fS0a = __half22float2(aS0a), fS0b = __half22float2(aS0b);
        float2 fS1a = __half22float2(aS1a), fS1b = __half22float2(aS1b);
        float2 fN0a = __half22float2(aN0a), fN0b = __half22float2(aN0b);
        float2 fN1a = __half22float2(aN1a), fN1b = __half22float2(aN1b);

        float s0 = fS0a.x + fS0b.x, s1 = fS0a.y + fS0b.y;
        float s2 = fS1a.x + fS1b.x, s3 = fS1a.y + fS1b.y;
        float n0 = fN0a.x + fN0b.x, n1 = fN0a.y + fN0b.y;
        float n2 = fN1a.x + fN1b.x, n3 = fN1a.y + fN1b.y;

        float r = 0.f;
        r += __saturatef(s0 + bb.x) * ws.x;
        r += __saturatef(s1 + bb.y) * ws.y;
        r += __saturatef(s2 + bb.z) * ws.z;
        r += __saturatef(s3 + bb.w) * ws.w;
        r += __saturatef(n0 + bb.x) * wn.x;
        r += __saturatef(n1 + bb.y) * wn.y;
        r += __saturatef(n2 + bb.z) * wn.z;
        r += __saturatef(n3 + bb.w) * wn.w;

        #pragma unroll
        for (int d = 16; d > 0; d >>= 1)
            r += __shfl_xor_sync(0xffffffffu, r, d);

        if (lane == 0) g_partial[chunk * BATCH + b] = r;
    }
}

// ---------------- epilogue: sum partials + sigmoid (float4) --------------
__global__ void epi_k(const float* __restrict__ out_b, float* __restrict__ out) {
    int t = blockIdx.x * blockDim.x + threadIdx.x;    // 8192 threads, 4 b each
    if (t < BATCH / 4) {
        const float bias = out_b[0];
        float4 s = ((const float4*)g_partial)[t];
        #pragma unroll
        for (int c = 1; c < NCHUNK; c++) {
            float4 p = ((const float4*)(g_partial + c * BATCH))[t];
            s.x += p.x; s.y += p.y; s.z += p.z; s.w += p.w;
        }
        float4 o;
        o.x = 1.f / (1.f + __expf(-(s.x + bias)));
        o.y = 1.f / (1.f + __expf(-(s.y + bias)));
        o.z = 1.f / (1.f + __expf(-(s.z + bias)));
        o.w = 1.f / (1.f + __expf(-(s.w + bias)));
        ((float4*)out)[t] = o;
    }
}

// ---------------- launch --------------------------------------------------
extern "C" void kernel_launch(void* const* d_in, const int* in_sizes, int n_in,
                              void* d_out, int out_size) {
    // Fixed leading inputs (dict order): stm_indices, nstm_indices, values.
    const int*   stm  = (const int*)d_in[0];   // [2, NNZ] int32 or int64 (sniffed)
    const int*   nstm = (const int*)d_in[1];
    const float* vals = (const float*)d_in[2];

    // Trailing inputs mapped by element count ("size" may or may not be a
    // real buffer). out_b is the LAST size-1 entry (dict order: size < out_b).
    const float* ft_w  = 0;
    const float* ft_b  = 0;
    const float* out_w = 0;
    const float* out_b = 0;
    for (int i = 3; i < n_in; i++) {
        int s = in_sizes[i];
        if      (s == NF * FT) ft_w  = (const float*)d_in[i];
        else if (s == FT)      ft_b  = (const float*)d_in[i];
        else if (s == 2 * FT)  out_w = (const float*)d_in[i];
        else if (s == 1)       out_b = (const float*)d_in[i];  // last wins
    }
    float* out = (float*)d_out;                  // [B, 1] float32

    prep_w<<<dim3(NF / 32, FT / 32), dim3(32, 8)>>>(ft_w);

    const int SMEM = NF * CHUNK * 2;   // 192 KB
    cudaFuncSetAttribute(main_k, cudaFuncAttributeMaxDynamicSharedMemorySize, SMEM);
    main_k<<<dim3(NBLK, NCHUNK), 512, SMEM>>>(stm, nstm, vals, ft_b, out_w);

    epi_k<<<(BATCH / 4 + 127) / 128, 128>>>(out_b, out);
}